// round 6
// baseline (speedup 1.0000x reference)
#include <cuda_runtime.h>
#include <cuda_bf16.h>
#include <cstdint>

#define N_ATOMS   50000
#define NUM_ELEM  10
#define LMAX      3
#define SH_DIM    16
#define CIN       128
#define COUT      128
#define TILE_M    128
#define NSEG      (NUM_ELEM * (LMAX + 1))
// tiles: sum_seg 2*ceil(rows/128) <= 2*(50000*16/128 + 40) = 12660
#define GRID_GEMM 12660
#define AS_STRIDE 132

__device__ int   g_counts[NUM_ELEM];
__device__ int   g_cursor[NUM_ELEM];
__device__ int   g_offsets[NUM_ELEM];
__device__ int   g_species[N_ATOMS];
__device__ int   g_order[N_ATOMS];
__device__ int   g_tile_prefix[NSEG + 1];
// W packed per-thread mma B-fragment layout: [seg][ks(8)][nt(16)][lane] -> {hi0,hi1,lo0,lo1}
__device__ uint4 g_wpack[NSEG * 4096];

// ---------------- helpers ----------------

__device__ __forceinline__ void split2(float a, float b, unsigned& hi, unsigned& lo) {
    __nv_bfloat16 ha = __float2bfloat16(a);
    __nv_bfloat16 hb = __float2bfloat16(b);
    __nv_bfloat162 hp; hp.x = ha; hp.y = hb;
    __nv_bfloat162 lp;
    lp.x = __float2bfloat16(a - __bfloat162float(ha));
    lp.y = __float2bfloat16(b - __bfloat162float(hb));
    hi = *(unsigned*)&hp;
    lo = *(unsigned*)&lp;
}

__device__ __forceinline__ void mma_bf16(float* c, const unsigned* a, unsigned b0, unsigned b1) {
    asm volatile(
        "mma.sync.aligned.m16n8k16.row.col.f32.bf16.bf16.f32 "
        "{%0,%1,%2,%3}, {%4,%5,%6,%7}, {%8,%9}, {%0,%1,%2,%3};\n"
        : "+f"(c[0]), "+f"(c[1]), "+f"(c[2]), "+f"(c[3])
        : "r"(a[0]), "r"(a[1]), "r"(a[2]), "r"(a[3]), "r"(b0), "r"(b1));
}

// ---------------- prep kernels ----------------

__global__ void k_init() {
    int t = threadIdx.x;
    if (t < NUM_ELEM) { g_counts[t] = 0; g_cursor[t] = 0; }
}

__global__ void k_hist(const float* __restrict__ y) {
    __shared__ int cnt[NUM_ELEM];
    int tid = threadIdx.x;
    if (tid < NUM_ELEM) cnt[tid] = 0;
    __syncthreads();
    int n = blockIdx.x * blockDim.x + tid;
    if (n < N_ATOMS) {
        const float* yr = y + (long)n * NUM_ELEM;
        float best = yr[0]; int s = 0;
#pragma unroll
        for (int e = 1; e < NUM_ELEM; e++) {
            float v = yr[e];
            if (v > best) { best = v; s = e; }
        }
        g_species[n] = s;
        atomicAdd(&cnt[s], 1);
    }
    __syncthreads();
    if (tid < NUM_ELEM && cnt[tid] > 0) atomicAdd(&g_counts[tid], cnt[tid]);
}

__global__ void k_scan() {
    if (threadIdx.x == 0) {
        int off = 0;
        for (int e = 0; e < NUM_ELEM; e++) { g_offsets[e] = off; off += g_counts[e]; }
        int tp = 0, seg = 0;
        g_tile_prefix[0] = 0;
        for (int e = 0; e < NUM_ELEM; e++)
            for (int l = 0; l <= LMAX; l++) {
                int rows = g_counts[e] * (2 * l + 1);
                tp += 2 * ((rows + TILE_M - 1) / TILE_M);  // x2 n-halves
                g_tile_prefix[++seg] = tp;
            }
    }
}

__global__ void k_scatter() {
    __shared__ int cnt[NUM_ELEM];
    __shared__ int base[NUM_ELEM];
    int tid = threadIdx.x;
    if (tid < NUM_ELEM) cnt[tid] = 0;
    __syncthreads();
    int n = blockIdx.x * blockDim.x + tid;
    int s = -1, myrank = 0;
    if (n < N_ATOMS) {
        s = g_species[n];
        myrank = atomicAdd(&cnt[s], 1);
    }
    __syncthreads();
    if (tid < NUM_ELEM) base[tid] = cnt[tid] ? atomicAdd(&g_cursor[tid], cnt[tid]) : 0;
    __syncthreads();
    if (n < N_ATOMS) g_order[g_offsets[s] + base[s] + myrank] = n;
}

// Pack W[e][l] into mma B-fragment layout (hi/lo bf16 split).
// Thread 'lane' of the mma needs B[k0..k0+1][n] and B[k0+8..k0+9][n]
// with k0 = 16*ks + 2*(lane&3), n = 8*nt + (lane>>2).
__global__ void k_wpack(const float* __restrict__ w) {
    int idx = blockIdx.x * blockDim.x + threadIdx.x;
    if (idx >= NSEG * 4096) return;
    int seg = idx >> 12;
    int rem = idx & 4095;
    int ks = rem >> 9;
    int nt = (rem >> 5) & 15;
    int t  = rem & 31;
    int k0 = ks * 16 + 2 * (t & 3);
    int n  = nt * 8 + (t >> 2);
    const float* W = w + (long)seg * CIN * COUT;
    float v0 = W[(k0    ) * COUT + n];
    float v1 = W[(k0 + 1) * COUT + n];
    float v2 = W[(k0 + 8) * COUT + n];
    float v3 = W[(k0 + 9) * COUT + n];
    unsigned h0, l0, h1, l1;
    split2(v0, v1, h0, l0);
    split2(v2, v3, h1, l1);
    g_wpack[idx] = make_uint4(h0, h1, l0, l1);
}

// ---------------- tensor-core tile GEMM ----------------
// CTA: 128 gathered rows x 64-col half of W[e,l]. 256 threads / 8 warps,
// 2 CTAs/SM (SMEM ~101KB) so fill/epilogue of one CTA overlaps the other's
// mainloop. Warp w: m-block (w&3)*32 rows (2 m-tiles), n-block (w>>2)*32 cols
// (4 n-tiles). bf16 hi/lo 3-pass in fp32 accum.

#define NB_FRAGS (8 * 8 * 32)  // ks * nt_local * lane = 2048 uint4 = 32KB
#define SMEM_BYTES (TILE_M * AS_STRIDE * 4 + NB_FRAGS * 16 + TILE_M * 4)

__global__ __launch_bounds__(256, 2)
void k_gemm(const float* __restrict__ x, float* __restrict__ out) {
    extern __shared__ char smem_raw[];
    float* As      = (float*)smem_raw;                               // [128][132]
    uint4* Bs      = (uint4*)(smem_raw + TILE_M * AS_STRIDE * 4);    // 2048 frags
    int*   rowbase = (int*)(Bs + NB_FRAGS);

    int t = blockIdx.x;
    if (t >= g_tile_prefix[NSEG]) return;
    int seg = 0;
    while (g_tile_prefix[seg + 1] <= t) seg++;
    int e = seg >> 2, l = seg & 3;
    int tt   = t - g_tile_prefix[seg];
    int row0 = (tt >> 1) * TILE_M;   // n-half innermost: pair CTAs share rows (L2 reuse of x)
    int nh0  = (tt & 1) * 8;         // first of 8 local n-tiles (64 cols)
    int R = 2 * l + 1;
    int Mseg = g_counts[e] * R;
    int offe = g_offsets[e];
    int tid = threadIdx.x;

    // per-row x base offsets
    if (tid < TILE_M) {
        int r = row0 + tid;
        int rb = -1;
        if (r < Mseg) {
            int atom = g_order[offe + r / R];
            rb = (atom * SH_DIM + l * l + r % R) * CIN;
        }
        rowbase[tid] = rb;
    }

    // B fill: copy this n-half's pre-packed frags (32KB, LDG.128 -> STS.128)
    {
        const uint4* wp = g_wpack + seg * 4096 + nh0 * 32;
#pragma unroll
        for (int ks = 0; ks < 8; ks++)
            Bs[ks * 256 + tid] = wp[ks * 512 + tid];
    }
    __syncthreads();

    // gather 128 x-rows fp32 (2 threads/row, 16 float4 each)
    {
        int m = tid >> 1, half = tid & 1;
        int rb = rowbase[m];
        float4* dst = (float4*)(As + m * AS_STRIDE) + half * 16;
        if (rb >= 0) {
            const float4* src = (const float4*)(x + rb) + half * 16;
#pragma unroll
            for (int i = 0; i < 16; i++) dst[i] = src[i];
        } else {
            float4 z = make_float4(0.f, 0.f, 0.f, 0.f);
#pragma unroll
            for (int i = 0; i < 16; i++) dst[i] = z;
        }
    }
    __syncthreads();

    int w    = tid >> 5;
    int lane = tid & 31;
    int g    = lane >> 2;
    int tig  = lane & 3;
    int mrow0 = (w & 3) * 32;        // 2 m-tiles per warp
    int nb    = (w >> 2) * 4;        // 4 local n-tiles per warp

    float acc[2][4][4];
#pragma unroll
    for (int m = 0; m < 2; m++)
#pragma unroll
        for (int nt = 0; nt < 4; nt++)
#pragma unroll
            for (int i = 0; i < 4; i++) acc[m][nt][i] = 0.f;

#pragma unroll
    for (int ks = 0; ks < 8; ks++) {
        unsigned ah[2][4], al[2][4];
#pragma unroll
        for (int m = 0; m < 2; m++) {
            const float* Ab = As + (mrow0 + m * 16) * AS_STRIDE + ks * 16;
            float2 p0 = *(const float2*)(Ab + (g    ) * AS_STRIDE + 2 * tig    );
            float2 p1 = *(const float2*)(Ab + (g + 8) * AS_STRIDE + 2 * tig    );
            float2 p2 = *(const float2*)(Ab + (g    ) * AS_STRIDE + 2 * tig + 8);
            float2 p3 = *(const float2*)(Ab + (g + 8) * AS_STRIDE + 2 * tig + 8);
            split2(p0.x, p0.y, ah[m][0], al[m][0]);
            split2(p1.x, p1.y, ah[m][1], al[m][1]);
            split2(p2.x, p2.y, ah[m][2], al[m][2]);
            split2(p3.x, p3.y, ah[m][3], al[m][3]);
        }
#pragma unroll
        for (int ntl = 0; ntl < 4; ntl++) {
            uint4 B = Bs[ks * 256 + (nb + ntl) * 32 + lane];
#pragma unroll
            for (int m = 0; m < 2; m++) {
                mma_bf16(acc[m][ntl], ah[m], B.x, B.y);   // Ah*Wh
                mma_bf16(acc[m][ntl], ah[m], B.z, B.w);   // Ah*Wl
                mma_bf16(acc[m][ntl], al[m], B.x, B.y);   // Al*Wh
            }
        }
    }

    const float scale = 0.08838834764831845f;  // 1/sqrt(128)
#pragma unroll
    for (int m = 0; m < 2; m++) {
        int rlo = rowbase[mrow0 + m * 16 + g];
        int rhi = rowbase[mrow0 + m * 16 + g + 8];
#pragma unroll
        for (int ntl = 0; ntl < 4; ntl++) {
            int col = (nh0 + nb + ntl) * 8 + 2 * tig;
            if (rlo >= 0)
                *(float2*)(out + rlo + col) =
                    make_float2(acc[m][ntl][0] * scale, acc[m][ntl][1] * scale);
            if (rhi >= 0)
                *(float2*)(out + rhi + col) =
                    make_float2(acc[m][ntl][2] * scale, acc[m][ntl][3] * scale);
        }
    }
}

// ---------------- launch ----------------

extern "C" void kernel_launch(void* const* d_in, const int* in_sizes, int n_in,
                              void* d_out, int out_size) {
    const float* x = (const float*)d_in[0];   // [N, 16, 128]
    const float* y = (const float*)d_in[1];   // [N, 10]
    const float* w = (const float*)d_in[2];   // [10, 4, 128, 128]
    float* out = (float*)d_out;               // [N, 16, 128]

    cudaFuncSetAttribute(k_gemm, cudaFuncAttributeMaxDynamicSharedMemorySize,
                         SMEM_BYTES);

    k_init<<<1, 32>>>();
    k_hist<<<(N_ATOMS + 255) / 256, 256>>>(y);
    k_scan<<<1, 32>>>();
    k_scatter<<<(N_ATOMS + 255) / 256, 256>>>();
    k_wpack<<<(NSEG * 4096 + 255) / 256, 256>>>(w);
    k_gemm<<<GRID_GEMM, 256, SMEM_BYTES>>>(x, out);
}

// round 7
// speedup vs baseline: 1.7905x; 1.7905x over previous
#include <cuda_runtime.h>
#include <cuda_bf16.h>
#include <cstdint>

#define N_ATOMS   50000
#define NUM_ELEM  10
#define LMAX      3
#define SH_DIM    16
#define CIN       128
#define COUT      128
#define TILE_M    128
#define NSEG      (NUM_ELEM * (LMAX + 1))
// tiles: sum_seg ceil(rows/128) <= 50000*16/128 + 40 = 6290
#define GRID_GEMM 6290

__device__ int   g_counts[NUM_ELEM];
__device__ int   g_cursor[NUM_ELEM];
__device__ int   g_offsets[NUM_ELEM];
__device__ int   g_species[N_ATOMS];
__device__ int   g_order[N_ATOMS];
__device__ int   g_tile_prefix[NSEG + 1];
// W packed in tf32 mma B-fragment layout:
// [seg][ks16(8)][nt(16)][lane(32)] -> uint4 {b_s0_lo, b_s0_hi, b_s1_lo, b_s1_hi}
__device__ uint4 g_wpack[NSEG * 4096];

// ---------------- helpers ----------------

__device__ __forceinline__ unsigned f2tf32(float v) {
    unsigned u;
    asm("cvt.rna.tf32.f32 %0, %1;" : "=r"(u) : "f"(v));
    return u;
}

__device__ __forceinline__ void mma_tf32(float* c, unsigned a0, unsigned a1,
                                         unsigned a2, unsigned a3,
                                         unsigned b0, unsigned b1) {
    asm volatile(
        "mma.sync.aligned.m16n8k8.row.col.f32.tf32.tf32.f32 "
        "{%0,%1,%2,%3}, {%4,%5,%6,%7}, {%8,%9}, {%0,%1,%2,%3};\n"
        : "+f"(c[0]), "+f"(c[1]), "+f"(c[2]), "+f"(c[3])
        : "r"(a0), "r"(a1), "r"(a2), "r"(a3), "r"(b0), "r"(b1));
}

// ---------------- prep kernels ----------------

__global__ void k_init() {
    int t = threadIdx.x;
    if (t < NUM_ELEM) { g_counts[t] = 0; g_cursor[t] = 0; }
}

__global__ void k_hist(const float* __restrict__ y) {
    __shared__ int cnt[NUM_ELEM];
    int tid = threadIdx.x;
    if (tid < NUM_ELEM) cnt[tid] = 0;
    __syncthreads();
    int n = blockIdx.x * blockDim.x + tid;
    if (n < N_ATOMS) {
        const float* yr = y + (long)n * NUM_ELEM;
        float best = yr[0]; int s = 0;
#pragma unroll
        for (int e = 1; e < NUM_ELEM; e++) {
            float v = yr[e];
            if (v > best) { best = v; s = e; }
        }
        g_species[n] = s;
        atomicAdd(&cnt[s], 1);
    }
    __syncthreads();
    if (tid < NUM_ELEM && cnt[tid] > 0) atomicAdd(&g_counts[tid], cnt[tid]);
}

__global__ void k_scan() {
    if (threadIdx.x == 0) {
        int off = 0;
        for (int e = 0; e < NUM_ELEM; e++) { g_offsets[e] = off; off += g_counts[e]; }
        int tp = 0, seg = 0;
        g_tile_prefix[0] = 0;
        for (int e = 0; e < NUM_ELEM; e++)
            for (int l = 0; l <= LMAX; l++) {
                int rows = g_counts[e] * (2 * l + 1);
                tp += (rows + TILE_M - 1) / TILE_M;
                g_tile_prefix[++seg] = tp;
            }
    }
}

__global__ void k_scatter() {
    __shared__ int cnt[NUM_ELEM];
    __shared__ int base[NUM_ELEM];
    int tid = threadIdx.x;
    if (tid < NUM_ELEM) cnt[tid] = 0;
    __syncthreads();
    int n = blockIdx.x * blockDim.x + tid;
    int s = -1, myrank = 0;
    if (n < N_ATOMS) {
        s = g_species[n];
        myrank = atomicAdd(&cnt[s], 1);
    }
    __syncthreads();
    if (tid < NUM_ELEM) base[tid] = cnt[tid] ? atomicAdd(&g_cursor[tid], cnt[tid]) : 0;
    __syncthreads();
    if (n < N_ATOMS) g_order[g_offsets[s] + base[s] + myrank] = n;
}

// Pack W[e][l] into tf32 mma B-fragment layout.
// For k8-step s, thread lane (g = lane>>2, tig = lane&3) of n-tile nt needs
// b0 = W[s*8 + tig][n], b1 = W[s*8 + tig + 4][n], n = nt*8 + g.
// uint4 holds both k8 steps of one K16 block: {s0.b0, s0.b1, s1.b0, s1.b1}.
__global__ void k_wpack(const float* __restrict__ w) {
    int idx = blockIdx.x * blockDim.x + threadIdx.x;
    if (idx >= NSEG * 4096) return;
    int seg = idx >> 12;
    int rem = idx & 4095;
    int ks = rem >> 9;          // K16 block
    int nt = (rem >> 5) & 15;
    int t  = rem & 31;
    int tig = t & 3;
    int n  = nt * 8 + (t >> 2);
    const float* W = w + (long)seg * CIN * COUT;
    int k0 = ks * 16;
    unsigned b00 = f2tf32(W[(k0 + tig     ) * COUT + n]);
    unsigned b01 = f2tf32(W[(k0 + tig + 4 ) * COUT + n]);
    unsigned b10 = f2tf32(W[(k0 + 8 + tig    ) * COUT + n]);
    unsigned b11 = f2tf32(W[(k0 + 8 + tig + 4) * COUT + n]);
    g_wpack[idx] = make_uint4(b00, b01, b10, b11);
}

// ---------------- tf32 tensor-core tile GEMM ----------------
// CTA: 128 gathered rows x full W[e,l] 128x128. 256 threads / 8 warps,
// 2 CTAs/SM (SMEM = B frags 64KB + rowbase). Warp w: m-block (w&3)*32 rows
// (2 m-tiles), n-block (w>>2)*64 cols (8 n-tiles). A loaded per-k-step
// directly from GMEM into registers (no A SMEM). Single tf32 pass.

#define SMEM_BYTES (4096 * 16 + TILE_M * 4)

__global__ __launch_bounds__(256, 2)
void k_gemm(const float* __restrict__ x, float* __restrict__ out) {
    extern __shared__ char smem_raw[];
    uint4* Bs      = (uint4*)smem_raw;        // [8][16][32] frags
    int*   rowbase = (int*)(Bs + 4096);

    int t = blockIdx.x;
    if (t >= g_tile_prefix[NSEG]) return;
    int seg = 0;
    while (g_tile_prefix[seg + 1] <= t) seg++;
    int e = seg >> 2, l = seg & 3;
    int row0 = (t - g_tile_prefix[seg]) * TILE_M;
    int R = 2 * l + 1;
    int Mseg = g_counts[e] * R;
    int offe = g_offsets[e];
    int tid = threadIdx.x;

    // per-row x base offsets
    if (tid < TILE_M) {
        int r = row0 + tid;
        int rb = -1;
        if (r < Mseg) {
            int atom = g_order[offe + r / R];
            rb = (atom * SH_DIM + l * l + r % R) * CIN;
        }
        rowbase[tid] = rb;
    }

    // B fill: 64KB linear copy of pre-packed frags
    {
        const uint4* wp = g_wpack + seg * 4096;
#pragma unroll
        for (int i = 0; i < 16; i++) Bs[tid + i * 256] = wp[tid + i * 256];
    }
    __syncthreads();

    int w    = tid >> 5;
    int lane = tid & 31;
    int g    = lane >> 2;
    int tig  = lane & 3;
    int mrow0 = (w & 3) * 32;       // 2 m-tiles
    int ntb   = (w >> 2) * 8;       // 8 n-tiles (64 cols)

    // this thread's 4 source rows
    int r0 = rowbase[mrow0 + g];
    int r1 = rowbase[mrow0 + g + 8];
    int r2 = rowbase[mrow0 + 16 + g];
    int r3 = rowbase[mrow0 + 16 + g + 8];

    float acc[2][8][4];
#pragma unroll
    for (int m = 0; m < 2; m++)
#pragma unroll
        for (int nt = 0; nt < 8; nt++)
#pragma unroll
            for (int i = 0; i < 4; i++) acc[m][nt][i] = 0.f;

#pragma unroll
    for (int ks = 0; ks < 8; ks++) {
        int c = ks * 16 + tig;
        // A fragments, straight from GMEM (predicated; invalid rows -> 0)
        float v[16];
#pragma unroll
        for (int s = 0; s < 2; s++) {   // k8 step
            int cc = c + s * 8;
            v[s * 4 + 0] = (r0 >= 0) ? __ldg(x + r0 + cc)     : 0.f;
            v[s * 4 + 1] = (r1 >= 0) ? __ldg(x + r1 + cc)     : 0.f;
            v[s * 4 + 2] = (r0 >= 0) ? __ldg(x + r0 + cc + 4) : 0.f;
            v[s * 4 + 3] = (r1 >= 0) ? __ldg(x + r1 + cc + 4) : 0.f;
            v[8 + s * 4 + 0] = (r2 >= 0) ? __ldg(x + r2 + cc)     : 0.f;
            v[8 + s * 4 + 1] = (r3 >= 0) ? __ldg(x + r3 + cc)     : 0.f;
            v[8 + s * 4 + 2] = (r2 >= 0) ? __ldg(x + r2 + cc + 4) : 0.f;
            v[8 + s * 4 + 3] = (r3 >= 0) ? __ldg(x + r3 + cc + 4) : 0.f;
        }
        unsigned u[16];
#pragma unroll
        for (int i = 0; i < 16; i++) u[i] = f2tf32(v[i]);

#pragma unroll
        for (int ntl = 0; ntl < 8; ntl++) {
            uint4 B = Bs[ks * 512 + (ntb + ntl) * 32 + lane];
            // m-tile 0
            mma_tf32(acc[0][ntl], u[0], u[1], u[2], u[3], B.x, B.y);
            mma_tf32(acc[0][ntl], u[4], u[5], u[6], u[7], B.z, B.w);
            // m-tile 1
            mma_tf32(acc[1][ntl], u[8], u[9], u[10], u[11], B.x, B.y);
            mma_tf32(acc[1][ntl], u[12], u[13], u[14], u[15], B.z, B.w);
        }
    }

    const float scale = 0.08838834764831845f;  // 1/sqrt(128)
#pragma unroll
    for (int m = 0; m < 2; m++) {
        int rlo = (m == 0) ? r0 : r2;
        int rhi = (m == 0) ? r1 : r3;
#pragma unroll
        for (int ntl = 0; ntl < 8; ntl++) {
            int col = (ntb + ntl) * 8 + 2 * tig;
            if (rlo >= 0)
                *(float2*)(out + rlo + col) =
                    make_float2(acc[m][ntl][0] * scale, acc[m][ntl][1] * scale);
            if (rhi >= 0)
                *(float2*)(out + rhi + col) =
                    make_float2(acc[m][ntl][2] * scale, acc[m][ntl][3] * scale);
        }
    }
}

// ---------------- launch ----------------

extern "C" void kernel_launch(void* const* d_in, const int* in_sizes, int n_in,
                              void* d_out, int out_size) {
    const float* x = (const float*)d_in[0];   // [N, 16, 128]
    const float* y = (const float*)d_in[1];   // [N, 10]
    const float* w = (const float*)d_in[2];   // [10, 4, 128, 128]
    float* out = (float*)d_out;               // [N, 16, 128]

    cudaFuncSetAttribute(k_gemm, cudaFuncAttributeMaxDynamicSharedMemorySize,
                         SMEM_BYTES);

    k_init<<<1, 32>>>();
    k_hist<<<(N_ATOMS + 255) / 256, 256>>>(y);
    k_scan<<<1, 32>>>();
    k_scatter<<<(N_ATOMS + 255) / 256, 256>>>();
    k_wpack<<<(NSEG * 4096 + 255) / 256, 256>>>(w);
    k_gemm<<<GRID_GEMM, 256, SMEM_BYTES>>>(x, out);
}